// round 1
// baseline (speedup 1.0000x reference)
#include <cuda_runtime.h>
#include <math.h>

// Problem constants (from reference: B=2, S=2048, D=1024, N=64, R=64, TOP_K=2)
#define TOKENS 4096
#define DIM    1024
#define NEXP   64
#define RANK   64
#define CAP    8192          // max picks an expert can receive (= total picks)
#define TILE_T 64            // tokens per projection tile
#define MAXTILES 256

#define OFF_IDX (TOKENS * RANK)            // 262144
#define OFF_W   (TOKENS * RANK + TOKENS*2) // 270336

// ---- scratch (device globals; no allocation allowed) ----
__device__ int   g_cnt[NEXP];
__device__ int   g_list[NEXP * CAP];   // stores pick slot p = token*2 + k
__device__ float g_w[TOKENS * 2];      // softmax weight per pick slot
__device__ int   g_ntiles;
__device__ int   g_tiles[MAXTILES];    // (expert<<16) | tile_index

// ============================================================
// Kernel 0: zero output accumulation region + expert counters
// ============================================================
__global__ void k_zero(float* __restrict__ out) {
    int i = blockIdx.x * blockDim.x + threadIdx.x;
    if (i < TOKENS * RANK) out[i] = 0.0f;
    if (i < NEXP) g_cnt[i] = 0;
}

// ============================================================
// Kernel 1: router scores (64 tokens x 64 experts per block),
//           top-2, softmax, scatter to per-expert lists.
// 256 threads, each computes a 4x4 register tile.
// ============================================================
__global__ __launch_bounds__(256) void k_router(
    const float* __restrict__ x,      // [TOKENS, DIM]
    const float* __restrict__ W,      // [NEXP, DIM]
    float* __restrict__ out, int out_size)
{
    __shared__ float xs[64][33];
    __shared__ float ws[64][33];
    __shared__ float sc[64][65];

    const int tid = threadIdx.x;
    const int ty  = tid >> 4;     // 0..15 -> token group
    const int tx  = tid & 15;     // 0..15 -> expert group
    const int tok0 = blockIdx.x * 64;

    float acc[4][4];
    #pragma unroll
    for (int i = 0; i < 4; i++)
        #pragma unroll
        for (int j = 0; j < 4; j++) acc[i][j] = 0.0f;

    for (int dc = 0; dc < DIM; dc += 32) {
        // load x tile: 64 rows x 32 cols = 512 float4, 2 per thread
        #pragma unroll
        for (int r = 0; r < 2; r++) {
            int idx = tid + r * 256;           // 0..511
            int t = idx >> 3, c = idx & 7;     // row, float4 col
            float4 v = *(const float4*)(x + (size_t)(tok0 + t) * DIM + dc + 4 * c);
            xs[t][4*c+0] = v.x; xs[t][4*c+1] = v.y; xs[t][4*c+2] = v.z; xs[t][4*c+3] = v.w;
            float4 u = *(const float4*)(W + (size_t)t * DIM + dc + 4 * c);
            ws[t][4*c+0] = u.x; ws[t][4*c+1] = u.y; ws[t][4*c+2] = u.z; ws[t][4*c+3] = u.w;
        }
        __syncthreads();

        #pragma unroll
        for (int k = 0; k < 32; k++) {
            float a[4], b[4];
            #pragma unroll
            for (int i = 0; i < 4; i++) a[i] = xs[ty*4 + i][k];
            #pragma unroll
            for (int j = 0; j < 4; j++) b[j] = ws[tx*4 + j][k];
            #pragma unroll
            for (int i = 0; i < 4; i++)
                #pragma unroll
                for (int j = 0; j < 4; j++)
                    acc[i][j] += a[i] * b[j];
        }
        __syncthreads();
    }

    // scores to smem
    #pragma unroll
    for (int i = 0; i < 4; i++)
        #pragma unroll
        for (int j = 0; j < 4; j++)
            sc[ty*4 + i][tx*4 + j] = acc[i][j];
    __syncthreads();

    // per-token top-2 + softmax + scatter
    if (tid < 64) {
        int t = tid;
        float m0 = -1e30f; int i0 = 0;
        #pragma unroll
        for (int n = 0; n < NEXP; n++) {
            float s = sc[t][n];
            if (s > m0) { m0 = s; i0 = n; }
        }
        float m1 = -1e30f; int i1 = 0;
        #pragma unroll
        for (int n = 0; n < NEXP; n++) {
            float s = sc[t][n];
            if (n != i0 && s > m1) { m1 = s; i1 = n; }
        }
        float w0 = 1.0f / (1.0f + __expf(m1 - m0));
        float w1 = 1.0f - w0;

        int token = tok0 + t;
        g_w[token*2 + 0] = w0;
        g_w[token*2 + 1] = w1;

        if (out_size >= OFF_IDX + TOKENS*2) {
            out[OFF_IDX + token*2 + 0] = (float)i0;
            out[OFF_IDX + token*2 + 1] = (float)i1;
        }
        if (out_size >= OFF_W + TOKENS*2) {
            out[OFF_W + token*2 + 0] = w0;
            out[OFF_W + token*2 + 1] = w1;
        }

        int p0 = atomicAdd(&g_cnt[i0], 1);
        g_list[i0 * CAP + p0] = token*2 + 0;
        int p1 = atomicAdd(&g_cnt[i1], 1);
        g_list[i1 * CAP + p1] = token*2 + 1;
    }
}

// ============================================================
// Kernel 1.5: build compacted (expert, tile) worklist
// ============================================================
__global__ void k_tiles() {
    __shared__ int s[NEXP];
    int e = threadIdx.x;   // 64 threads
    int nt = (g_cnt[e] + TILE_T - 1) / TILE_T;
    s[e] = nt;
    __syncthreads();
    if (e == 0) {
        int sum = 0;
        for (int i = 0; i < NEXP; i++) { int v = s[i]; s[i] = sum; sum += v; }
        g_ntiles = sum;
    }
    __syncthreads();
    int base = s[e];
    for (int j = 0; j < nt; j++) g_tiles[base + j] = (e << 16) | j;
}

// ============================================================
// Kernel 2: projection. Persistent blocks over worklist.
// One tile = (expert e, up to 64 tokens). neurons[e] streamed
// through SMEM in 64-d chunks; 64x64 register-tiled GEMM.
// ============================================================
__global__ __launch_bounds__(256) void k_proj(
    const float* __restrict__ x,        // [TOKENS, DIM]
    const float* __restrict__ neurons,  // [NEXP, DIM, RANK]
    float* __restrict__ out)
{
    __shared__ float xsh[TILE_T][64];   // 16 KB
    __shared__ float nsh[64][RANK];     // 16 KB
    __shared__ int   tsh[TILE_T];
    __shared__ float wsh[TILE_T];

    const int tid = threadIdx.x;
    const int ty  = tid >> 4;   // 0..15 -> token group (4 tokens)
    const int tx  = tid & 15;   // 0..15 -> r group (4 consecutive r)
    const int ntiles = g_ntiles;

    for (int it = blockIdx.x; it < ntiles; it += gridDim.x) {
        int ent = g_tiles[it];
        int e = ent >> 16;
        int off = (ent & 0xffff) * TILE_T;
        int cnt = g_cnt[e] - off;
        if (cnt > TILE_T) cnt = TILE_T;

        if (tid < TILE_T) {
            if (tid < cnt) {
                int p = g_list[e * CAP + off + tid];
                tsh[tid] = p >> 1;
                wsh[tid] = g_w[p];
            } else {
                tsh[tid] = -1;
                wsh[tid] = 0.0f;
            }
        }
        __syncthreads();

        float acc[4][4];
        #pragma unroll
        for (int i = 0; i < 4; i++)
            #pragma unroll
            for (int j = 0; j < 4; j++) acc[i][j] = 0.0f;

        const float* nbase = neurons + (size_t)e * DIM * RANK;
        const int myTok[4] = { tsh[ty*4+0], tsh[ty*4+1], tsh[ty*4+2], tsh[ty*4+3] };

        for (int dc = 0; dc < DIM; dc += 64) {
            // neurons chunk: 64x64 = 1024 float4, 4 per thread (contiguous)
            {
                const float4* ng = (const float4*)(nbase + (size_t)dc * RANK);
                float4* nd = (float4*)&nsh[0][0];
                #pragma unroll
                for (int k = 0; k < 4; k++)
                    nd[tid + k * 256] = ng[tid + k * 256];
            }
            // x chunk: 64 token rows x 64 floats; 4 threads per token row
            {
                int t = tid >> 2;
                int l = tid & 3;
                int tok = tsh[t];
                float4* xd = (float4*)&xsh[t][0];
                if (tok >= 0) {
                    const float4* xg = (const float4*)(x + (size_t)tok * DIM + dc);
                    #pragma unroll
                    for (int k = 0; k < 4; k++)
                        xd[l + k * 4] = xg[l + k * 4];
                } else {
                    float4 z = make_float4(0.f, 0.f, 0.f, 0.f);
                    #pragma unroll
                    for (int k = 0; k < 4; k++)
                        xd[l + k * 4] = z;
                }
            }
            __syncthreads();

            #pragma unroll 8
            for (int d = 0; d < 64; d++) {
                float4 nv = *(const float4*)&nsh[d][tx * 4];
                float a0 = xsh[ty*4 + 0][d];
                float a1 = xsh[ty*4 + 1][d];
                float a2 = xsh[ty*4 + 2][d];
                float a3 = xsh[ty*4 + 3][d];
                acc[0][0] += a0 * nv.x; acc[0][1] += a0 * nv.y; acc[0][2] += a0 * nv.z; acc[0][3] += a0 * nv.w;
                acc[1][0] += a1 * nv.x; acc[1][1] += a1 * nv.y; acc[1][2] += a1 * nv.z; acc[1][3] += a1 * nv.w;
                acc[2][0] += a2 * nv.x; acc[2][1] += a2 * nv.y; acc[2][2] += a2 * nv.z; acc[2][3] += a2 * nv.w;
                acc[3][0] += a3 * nv.x; acc[3][1] += a3 * nv.y; acc[3][2] += a3 * nv.z; acc[3][3] += a3 * nv.w;
            }
            __syncthreads();
        }

        // epilogue: out[tok, r] += w * acc   (exactly 2 adds per element
        // across whole grid, onto zero-init -> commutative -> deterministic)
        #pragma unroll
        for (int i = 0; i < 4; i++) {
            int tok = myTok[i];
            if (tok >= 0) {
                float w = wsh[ty*4 + i];
                #pragma unroll
                for (int j = 0; j < 4; j++)
                    atomicAdd(&out[(size_t)tok * RANK + tx*4 + j], w * acc[i][j]);
            }
        }
        __syncthreads();  // protect tsh/wsh before next tile
    }
}

// ============================================================
extern "C" void kernel_launch(void* const* d_in, const int* in_sizes, int n_in,
                              void* d_out, int out_size) {
    const float* x       = (const float*)d_in[0];  // [2,2048,1024]
    const float* router  = (const float*)d_in[1];  // [64,1024]
    const float* neurons = (const float*)d_in[2];  // [64,1024,64]
    float* out = (float*)d_out;

    k_zero<<<(TOKENS * RANK + 255) / 256, 256>>>(out);
    k_router<<<TOKENS / 64, 256>>>(x, router, out, out_size);
    k_tiles<<<1, NEXP>>>();
    k_proj<<<256, 256>>>(x, neurons, out);
}

// round 2
// speedup vs baseline: 1.4036x; 1.4036x over previous
#include <cuda_runtime.h>
#include <math.h>

// Problem: B=2,S=2048,D=1024, N_COMPRESS=64, RANK=64, TOP_K=2
#define TOKENS 4096
#define DIM    1024
#define NEXP   64
#define RANK   64
#define CAP    8192
#define TILE_T 64
#define MAXTILES 256
#define NSPLIT 4          // split-K for projection (D/4 = 256 each)
#define DSPL   256

#define OFF_IDX (TOKENS * RANK)
#define OFF_W   (TOKENS * RANK + TOKENS*2)

typedef unsigned long long ull;

__device__ __forceinline__ ull fma2(ull a, ull b, ull c) {
    ull d; asm("fma.rn.f32x2 %0, %1, %2, %3;" : "=l"(d) : "l"(a), "l"(b), "l"(c)); return d;
}
__device__ __forceinline__ float2 unpack2(ull v) {
    float2 r; asm("mov.b64 {%0, %1}, %2;" : "=f"(r.x), "=f"(r.y) : "l"(v)); return r;
}

// ---- scratch (device globals) ----
__device__ int   g_cnt[NEXP];
__device__ int   g_list[NEXP * CAP];
__device__ float g_w[TOKENS * 2];
__device__ int   g_ntiles;
__device__ int   g_tiles[MAXTILES];
__device__ float g_part[2 * TOKENS * NEXP];            // router partial scores (2 D-splits)
__device__ float g_scratch[NSPLIT * TOKENS * 2 * RANK]; // proj partials per (split, pick)

// ============================================================
// Kernel 0: zero expert counters
// ============================================================
__global__ void k_zero() {
    if (threadIdx.x < NEXP) g_cnt[threadIdx.x] = 0;
}

// ============================================================
// Kernel 1: router partial scores. grid (64 token-blocks, 2 D-splits).
// 64 tokens x 64 experts per block over D range of 512.
// f32x2 FMAs paired over the reduction dim k (both operands contiguous).
// ============================================================
__global__ __launch_bounds__(256) void k_router(
    const float* __restrict__ x, const float* __restrict__ W)
{
    __shared__ float xs[64][34];   // pad 34 (even) -> 8B-aligned rows, no bank conflicts
    __shared__ float ws[64][34];

    const int tid = threadIdx.x;
    const int ty  = tid >> 4;     // 0..15
    const int tx  = tid & 15;     // 0..15
    const int tok0 = blockIdx.x * 64;
    const int d0   = blockIdx.y * 512;

    ull acc[4][4];
    #pragma unroll
    for (int i = 0; i < 4; i++)
        #pragma unroll
        for (int j = 0; j < 4; j++) acc[i][j] = 0ull;

    for (int dc = 0; dc < 512; dc += 32) {
        #pragma unroll
        for (int r = 0; r < 2; r++) {
            int idx = tid + r * 256;           // 0..511
            int t = idx >> 3, c = idx & 7;
            float4 v = *(const float4*)(x + (size_t)(tok0 + t) * DIM + d0 + dc + 4 * c);
            xs[t][4*c+0] = v.x; xs[t][4*c+1] = v.y; xs[t][4*c+2] = v.z; xs[t][4*c+3] = v.w;
            float4 u = *(const float4*)(W + (size_t)t * DIM + d0 + dc + 4 * c);
            ws[t][4*c+0] = u.x; ws[t][4*c+1] = u.y; ws[t][4*c+2] = u.z; ws[t][4*c+3] = u.w;
        }
        __syncthreads();

        #pragma unroll
        for (int k = 0; k < 32; k += 2) {
            ull a[4], b[4];
            #pragma unroll
            for (int i = 0; i < 4; i++) a[i] = *(const ull*)&xs[ty + 16*i][k];
            #pragma unroll
            for (int j = 0; j < 4; j++) b[j] = *(const ull*)&ws[tx + 16*j][k];
            #pragma unroll
            for (int i = 0; i < 4; i++)
                #pragma unroll
                for (int j = 0; j < 4; j++)
                    acc[i][j] = fma2(a[i], b[j], acc[i][j]);
        }
        __syncthreads();
    }

    float* dst = g_part + (size_t)blockIdx.y * TOKENS * NEXP + (size_t)tok0 * NEXP;
    #pragma unroll
    for (int i = 0; i < 4; i++)
        #pragma unroll
        for (int j = 0; j < 4; j++) {
            float2 p = unpack2(acc[i][j]);
            dst[(ty + 16*i) * NEXP + tx + 16*j] = p.x + p.y;
        }
}

// ============================================================
// Kernel 1.25: combine partials, top-2, softmax, outputs, scatter.
// ============================================================
__global__ __launch_bounds__(256) void k_top2(float* __restrict__ out, int out_size) {
    int t = blockIdx.x * blockDim.x + threadIdx.x;   // 0..4095
    const float4* p0 = (const float4*)(g_part) + (size_t)t * 16;
    const float4* p1 = (const float4*)(g_part + (size_t)TOKENS * NEXP) + (size_t)t * 16;

    float m0 = -1e30f, m1 = -1e30f; int i0 = 0, i1 = 0;
    #pragma unroll
    for (int c = 0; c < 16; c++) {
        float4 a = p0[c], b = p1[c];
        float s[4] = { a.x + b.x, a.y + b.y, a.z + b.z, a.w + b.w };
        #pragma unroll
        for (int e = 0; e < 4; e++) {
            int n = 4*c + e;
            float v = s[e];
            if (v > m0)      { m1 = m0; i1 = i0; m0 = v; i0 = n; }
            else if (v > m1) { m1 = v; i1 = n; }
        }
    }
    float w0 = 1.0f / (1.0f + __expf(m1 - m0));
    float w1 = 1.0f - w0;

    g_w[t*2 + 0] = w0;
    g_w[t*2 + 1] = w1;
    if (out_size >= OFF_IDX + TOKENS*2) {
        out[OFF_IDX + t*2 + 0] = (float)i0;
        out[OFF_IDX + t*2 + 1] = (float)i1;
    }
    if (out_size >= OFF_W + TOKENS*2) {
        out[OFF_W + t*2 + 0] = w0;
        out[OFF_W + t*2 + 1] = w1;
    }
    int p = atomicAdd(&g_cnt[i0], 1);
    g_list[i0 * CAP + p] = t*2 + 0;
    p = atomicAdd(&g_cnt[i1], 1);
    g_list[i1 * CAP + p] = t*2 + 1;
}

// ============================================================
// Kernel 1.5: compacted (expert, tile) worklist
// ============================================================
__global__ void k_tiles() {
    __shared__ int s[NEXP];
    int e = threadIdx.x;
    int nt = (g_cnt[e] + TILE_T - 1) / TILE_T;
    s[e] = nt;
    __syncthreads();
    if (e == 0) {
        int sum = 0;
        for (int i = 0; i < NEXP; i++) { int v = s[i]; s[i] = sum; sum += v; }
        g_ntiles = sum;
    }
    __syncthreads();
    int base = s[e];
    for (int j = 0; j < nt; j++) g_tiles[base + j] = (e << 16) | j;
}

// ============================================================
// Kernel 2: projection, split-K x4, persistent blocks.
// neurons transposed in SMEM so the d-reduction is contiguous ->
// pure f32x2 FMAs, no pack MOVs. Partials to disjoint scratch rows.
// ============================================================
__global__ __launch_bounds__(256) void k_proj(
    const float* __restrict__ x, const float* __restrict__ neurons)
{
    __shared__ float xsh[TILE_T][68];   // pad 68: 16B-aligned rows, conflict-free a-reads
    __shared__ float nshT[RANK][66];    // transposed neurons chunk, pad 66 (8B-aligned)
    __shared__ int   tsh[TILE_T];
    __shared__ int   psh[TILE_T];

    const int tid = threadIdx.x;
    const int ty  = tid >> 4;
    const int tx  = tid & 15;
    const int nwork = g_ntiles * NSPLIT;

    for (int w = blockIdx.x; w < nwork; w += gridDim.x) {
        const int it = w >> 2;
        const int sp = w & 3;
        const int ent = g_tiles[it];
        const int e   = ent >> 16;
        const int off = (ent & 0xffff) * TILE_T;
        int cnt = g_cnt[e] - off;
        if (cnt > TILE_T) cnt = TILE_T;

        if (tid < TILE_T) {
            if (tid < cnt) {
                int p = g_list[e * CAP + off + tid];
                psh[tid] = p;
                tsh[tid] = p >> 1;
            } else {
                psh[tid] = -1;
                tsh[tid] = -1;
            }
        }
        __syncthreads();

        ull acc[4][4];
        #pragma unroll
        for (int i = 0; i < 4; i++)
            #pragma unroll
            for (int j = 0; j < 4; j++) acc[i][j] = 0ull;

        const float* nbase = neurons + ((size_t)e * DIM + (size_t)sp * DSPL) * RANK;
        int myP[4];
        #pragma unroll
        for (int i = 0; i < 4; i++) myP[i] = psh[ty + 16*i];

        for (int dc = 0; dc < DSPL; dc += 64) {
            // neurons chunk [64 d][64 r] -> transposed SMEM [r][d]
            {
                const float* ng = nbase + (size_t)dc * RANK;
                #pragma unroll
                for (int k = 0; k < 4; k++) {
                    int idx = tid + 256 * k;       // 0..1023
                    int d = idx >> 4, rc = idx & 15;
                    float4 v = *(const float4*)(ng + d * RANK + rc * 4);
                    nshT[4*rc+0][d] = v.x;
                    nshT[4*rc+1][d] = v.y;
                    nshT[4*rc+2][d] = v.z;
                    nshT[4*rc+3][d] = v.w;
                }
            }
            // x chunk: 64 gathered token rows x 64 floats
            {
                int t = tid >> 2, l = tid & 3;
                int tok = tsh[t];
                float4* xd = (float4*)&xsh[t][0];
                if (tok >= 0) {
                    const float4* xg = (const float4*)(x + (size_t)tok * DIM + sp * DSPL + dc);
                    #pragma unroll
                    for (int k = 0; k < 4; k++) xd[l + 4*k] = xg[l + 4*k];
                } else {
                    float4 z = make_float4(0.f, 0.f, 0.f, 0.f);
                    #pragma unroll
                    for (int k = 0; k < 4; k++) xd[l + 4*k] = z;
                }
            }
            __syncthreads();

            #pragma unroll 8
            for (int d = 0; d < 64; d += 2) {
                ull a[4], b[4];
                #pragma unroll
                for (int i = 0; i < 4; i++) a[i] = *(const ull*)&xsh[ty + 16*i][d];
                #pragma unroll
                for (int j = 0; j < 4; j++) b[j] = *(const ull*)&nshT[tx + 16*j][d];
                #pragma unroll
                for (int i = 0; i < 4; i++)
                    #pragma unroll
                    for (int j = 0; j < 4; j++)
                        acc[i][j] = fma2(a[i], b[j], acc[i][j]);
            }
            __syncthreads();
        }

        // write raw partials to disjoint (split, pick) scratch rows
        float* sb = g_scratch + (size_t)sp * (TOKENS * 2) * RANK;
        #pragma unroll
        for (int i = 0; i < 4; i++) {
            int p = myP[i];
            if (p >= 0) {
                #pragma unroll
                for (int j = 0; j < 4; j++) {
                    float2 v = unpack2(acc[i][j]);
                    sb[(size_t)p * RANK + tx + 16*j] = v.x + v.y;
                }
            }
        }
        __syncthreads();
    }
}

// ============================================================
// Kernel 3: deterministic reduce: out[t,r] = sum_k w_k * sum_s scratch[s, t*2+k, r]
// ============================================================
__global__ __launch_bounds__(256) void k_reduce(float* __restrict__ out) {
    int i = blockIdx.x * blockDim.x + threadIdx.x;  // 0..65535
    int t = i >> 4;
    int c = (i & 15) * 4;
    float4 acc = make_float4(0.f, 0.f, 0.f, 0.f);
    #pragma unroll
    for (int k = 0; k < 2; k++) {
        int p = t*2 + k;
        float w = g_w[p];
        #pragma unroll
        for (int s = 0; s < NSPLIT; s++) {
            float4 v = *(const float4*)&g_scratch[((size_t)s * (TOKENS*2) + p) * RANK + c];
            acc.x += w * v.x; acc.y += w * v.y; acc.z += w * v.z; acc.w += w * v.w;
        }
    }
    *(float4*)&out[(size_t)t * RANK + c] = acc;
}

// ============================================================
extern "C" void kernel_launch(void* const* d_in, const int* in_sizes, int n_in,
                              void* d_out, int out_size) {
    const float* x       = (const float*)d_in[0];
    const float* router  = (const float*)d_in[1];
    const float* neurons = (const float*)d_in[2];
    float* out = (float*)d_out;

    k_zero<<<1, 64>>>();
    k_router<<<dim3(TOKENS/64, 2), 256>>>(x, router);
    k_top2<<<TOKENS/256, 256>>>(out, out_size);
    k_tiles<<<1, NEXP>>>();
    k_proj<<<592, 256>>>(x, neurons);
    k_reduce<<<TOKENS*RANK/4/256, 256>>>(out);
}